// round 11
// baseline (speedup 1.0000x reference)
#include <cuda_runtime.h>
#include <cuda_fp16.h>
#include <cstdint>

// Problem constants
#define BB 2
#define TT 2048
#define CC 1024
#define HH 16
#define DD 64
#define MM (BB*TT)

// Scratch (static __device__ — no runtime allocation). fp16 everywhere.
__device__ __half g_xh[MM*CC];
__device__ __half g_wqh[HH*CC*DD];
__device__ __half g_wkh[HH*CC*DD];
__device__ __half g_wvh[HH*CC*DD];
__device__ __half g_wph[CC*CC];
__device__ __half g_q[BB*HH*TT*DD];     // [B,H,T,D]
__device__ __half g_k[BB*HH*TT*DD];
__device__ __half g_v[BB*HH*TT*DD];
__device__ __half g_att[BB*TT*CC];      // [B,T,C]

// ---------------------------------------------------------------------------
// helpers
// ---------------------------------------------------------------------------
__device__ __forceinline__ void mma_f16(float* d, const uint32_t* a, const uint32_t* b) {
    asm volatile(
        "mma.sync.aligned.m16n8k16.row.col.f32.f16.f16.f32 "
        "{%0,%1,%2,%3}, {%4,%5,%6,%7}, {%8,%9}, {%0,%1,%2,%3};"
        : "+f"(d[0]), "+f"(d[1]), "+f"(d[2]), "+f"(d[3])
        : "r"(a[0]), "r"(a[1]), "r"(a[2]), "r"(a[3]),
          "r"(b[0]), "r"(b[1]));
}
__device__ __forceinline__ void ldm_x4(uint32_t* r, uint32_t addr) {
    asm volatile(
        "ldmatrix.sync.aligned.m8n8.x4.shared.b16 {%0,%1,%2,%3}, [%4];"
        : "=r"(r[0]), "=r"(r[1]), "=r"(r[2]), "=r"(r[3]) : "r"(addr));
}
__device__ __forceinline__ void ldm_x4_t(uint32_t* r, uint32_t addr) {
    asm volatile(
        "ldmatrix.sync.aligned.m8n8.x4.trans.shared.b16 {%0,%1,%2,%3}, [%4];"
        : "=r"(r[0]), "=r"(r[1]), "=r"(r[2]), "=r"(r[3]) : "r"(addr));
}
__device__ __forceinline__ uint32_t pack_h2(float a, float b) {
    __half2 h = __floats2half2_rn(a, b);
    return *(uint32_t*)&h;
}
__device__ __forceinline__ void cp16(uint32_t dst, const void* src) {
    asm volatile("cp.async.cg.shared.global [%0], [%1], 16;" :: "r"(dst), "l"(src));
}
__device__ __forceinline__ void cp_commit() {
    asm volatile("cp.async.commit_group;");
}
template<int N> __device__ __forceinline__ void cp_wait() {
    asm volatile("cp.async.wait_group %0;" :: "n"(N));
}

// ---------------------------------------------------------------------------
// Fused fp32 -> fp16 conversion (one launch for all five tensors)
// ---------------------------------------------------------------------------
__global__ void cvt_all(const float4* __restrict__ x,  const float4* __restrict__ wq,
                        const float4* __restrict__ wk, const float4* __restrict__ wv,
                        const float4* __restrict__ wp)
{
    const int N_X = MM * CC / 4;
    const int N_W = HH * CC * DD / 4;
    const int N_P = CC * CC / 4;
    const int total = N_X + 3 * N_W + N_P;
    int i = blockIdx.x * blockDim.x + threadIdx.x;
    const int stride = gridDim.x * blockDim.x;
    for (; i < total; i += stride) {
        const float4* src; uint2* dst; int j = i;
        if (j < N_X)              { src = x;  dst = (uint2*)g_xh; }
        else if ((j -= N_X) < N_W){ src = wq; dst = (uint2*)g_wqh; }
        else if ((j -= N_W) < N_W){ src = wk; dst = (uint2*)g_wkh; }
        else if ((j -= N_W) < N_W){ src = wv; dst = (uint2*)g_wvh; }
        else                      { j -= N_W; src = wp; dst = (uint2*)g_wph; }
        float4 v = src[j];
        uint2 r;
        r.x = pack_h2(v.x, v.y);
        r.y = pack_h2(v.z, v.w);
        dst[j] = r;
    }
}

// ---------------------------------------------------------------------------
// GEMM (fp16 MMA, 3-stage cp.async, BK=16, ONE barrier per iteration).
// BM=128, BN=128. 256 threads = 8 warps; warp tile 32(m) x 64(n).
// ---------------------------------------------------------------------------
#define SA_H 24
#define SB_H 136
#define NSTG 3

template<int IS_QKV>
__global__ __launch_bounds__(256, 2) void gemm_tc(
    const float* __restrict__ bp,
    float* __restrict__ out)
{
    __shared__ __half As[NSTG][128 * SA_H];   // 3 x 6.0 KB
    __shared__ __half Bs[NSTG][16 * SB_H];    // 3 x 4.25 KB

    const int tid  = threadIdx.x;
    const int lane = tid & 31;
    const int warp = tid >> 5;          // 0..7
    const int wm = warp & 3;            // m strip (0..3) of 32 rows
    const int wn = warp >> 2;           // n strip (0..1) of 64 cols
    const int g  = lane >> 2;
    const int tg = lane & 3;

    const int m0 = blockIdx.y * 128;
    const int n0 = blockIdx.x * 128;

    const __half* A = IS_QKV ? g_xh : g_att;
    const __half* W;
    int h0 = 0, sel = 0;
    if (IS_QKV) {
        sel = n0 >> 10;
        h0  = (n0 & 1023) >> 6;
        W   = (sel == 0 ? g_wqh : (sel == 1 ? g_wkh : g_wvh));
    } else {
        W = g_wph;
    }

    // cp.async mapping (256 threads, one 16B chunk each)
    const int a_r  = tid >> 1;              // 0..127
    const int a_c8 = (tid & 1) * 8;
    const int b_r  = tid >> 4;              // 0..15
    const int b_c8 = (tid & 15) * 8;

    const int lrow  = (lane & 7) + ((lane >> 3) & 1) * 8;
    const int lcol8 = ((lane >> 4) & 1) * 8;
    const uint32_t a_base = (uint32_t)__cvta_generic_to_shared(&As[0][0]);
    const uint32_t b_base = (uint32_t)__cvta_generic_to_shared(&Bs[0][0]);
    const uint32_t ABUF = 128 * SA_H * 2;
    const uint32_t BBUF = 16 * SB_H * 2;

    auto load_stage = [&](int k0, int st) {
        cp16(a_base + st * ABUF + (a_r * SA_H + a_c8) * 2,
             &A[(m0 + a_r) * CC + k0 + a_c8]);
        const __half* src;
        if (IS_QKV) {
            int h = h0 + (b_c8 >> 6);
            int d = b_c8 & 63;
            src = &W[(h * CC + (k0 + b_r)) * DD + d];
        } else {
            src = &W[(k0 + b_r) * CC + n0 + b_c8];
        }
        cp16(b_base + st * BBUF + (b_r * SB_H + b_c8) * 2, src);
    };

    float acc[2][8][4] = {};

    load_stage(0, 0);  cp_commit();
    load_stage(16, 1); cp_commit();

    const int NIT = CC / 16;   // 64
    for (int it = 0; it < NIT; it++) {
        cp_wait<1>();
        __syncthreads();

        if (it + 2 < NIT) load_stage((it + 2) * 16, (it + 2) % NSTG);
        cp_commit();

        const int st = it % NSTG;
        uint32_t af[2][4];
        #pragma unroll
        for (int mt = 0; mt < 2; mt++) {
            int row = wm * 32 + mt * 16 + lrow;
            ldm_x4(af[mt], a_base + st * ABUF + (row * SA_H + lcol8) * 2);
        }
        uint32_t bf[4][4];
        #pragma unroll
        for (int np = 0; np < 4; np++) {
            int col = wn * 64 + np * 16 + lcol8;
            ldm_x4_t(bf[np], b_base + st * BBUF + (lrow * SB_H + col) * 2);
        }
        #pragma unroll
        for (int nt = 0; nt < 8; nt++) {
            const uint32_t* bb = &bf[nt >> 1][(nt & 1) * 2];
            mma_f16(acc[0][nt], af[0], bb);
            mma_f16(acc[1][nt], af[1], bb);
        }
    }

    // ---- epilogue ----
    #pragma unroll
    for (int mt = 0; mt < 2; mt++) {
        int mm = m0 + wm * 32 + mt * 16 + g;
        if (IS_QKV) {
            __half* outBuf = (sel == 0 ? g_q : (sel == 1 ? g_k : g_v));
            int b = mm >> 11;
            int t = mm & 2047;
            int h = h0 + wn;
            #pragma unroll
            for (int nt = 0; nt < 8; nt++) {
                int d = nt * 8 + 2 * tg;
                *(uint32_t*)&outBuf[((b * HH + h) * TT + t) * DD + d] =
                    pack_h2(acc[mt][nt][0], acc[mt][nt][1]);
                *(uint32_t*)&outBuf[((b * HH + h) * TT + t + 8) * DD + d] =
                    pack_h2(acc[mt][nt][2], acc[mt][nt][3]);
            }
        } else {
            #pragma unroll
            for (int nt = 0; nt < 8; nt++) {
                int col = n0 + wn * 64 + nt * 8 + 2 * tg;
                float b0 = bp[col], b1 = bp[col + 1];
                *(float2*)&out[mm * CC + col] =
                    make_float2(acc[mt][nt][0] + b0, acc[mt][nt][1] + b1);
                *(float2*)&out[(mm + 8) * CC + col] =
                    make_float2(acc[mt][nt][2] + b0, acc[mt][nt][3] + b1);
            }
        }
    }
}

// ---------------------------------------------------------------------------
// Flash attention (causal), fp16 MMA, 3-stage swizzled KV pipeline.
// 256 threads = 8 warps; 128 queries per CTA (16 rows/warp); 64-key tiles.
// Each KV tile-load serves 128 queries (2x reuse vs 64q blocks).
// Softmax in exp2 domain (log2(e)/8 folded into Q scale).
// ---------------------------------------------------------------------------
#define KVSTG 3

__device__ __forceinline__ uint32_t swz(int row, int chunk) {
    return (uint32_t)(row * 128 + ((chunk ^ (row & 7)) << 4));
}

__global__ __launch_bounds__(256, 2) void attn_tc()
{
    __shared__ __half Ks[KVSTG][64 * 64];   // 3 x 8 KB
    __shared__ __half Vs[KVSTG][64 * 64];   // 3 x 8 KB  (48 KB total)

    const int tid  = threadIdx.x;
    const int lane = tid & 31;
    const int warp = tid >> 5;          // 0..7
    const int g  = lane >> 2;
    const int tg = lane & 3;

    const int bx  = blockIdx.x;         // 0..15
    const int bh  = blockIdx.y;
    const int qt0 = bx * 128;
    const int njt = 2 * bx + 2;         // key tiles for this block

    const uint32_t ks_base = (uint32_t)__cvta_generic_to_shared(&Ks[0][0]);
    const uint32_t vs_base = (uint32_t)__cvta_generic_to_shared(&Vs[0][0]);
    const uint32_t KBUF = 64 * 64 * 2;
    const int lrowA  = (lane & 7) + ((lane >> 3) & 1) * 8;
    const int lcol8A = ((lane >> 4) & 1) * 8;
    const int lrowK  = (lane & 7) + ((lane >> 4) & 1) * 8;
    const int lcol8K = ((lane >> 3) & 1) * 8;

    // cp.async mapping: 64 rows x 8 chunks = 512 ops, 256 threads x 2 passes
    const int t_r = tid >> 3;               // 0..31 (+32)
    const int t_c = tid & 7;

    auto load_kv = [&](int jt, int st) {
        const __half* kb = &g_k[(bh * TT + jt * 64) * DD];
        const __half* vb = &g_v[(bh * TT + jt * 64) * DD];
        #pragma unroll
        for (int p = 0; p < 2; p++) {
            int r = t_r + p * 32;
            cp16(ks_base + st * KBUF + swz(r, t_c), &kb[r * DD + t_c * 8]);
            cp16(vs_base + st * KBUF + swz(r, t_c), &vb[r * DD + t_c * 8]);
        }
    };

    // --- stage Q (scale = log2(e)/8) into Ks[0..1], extract A-frags ---
    {
        const __half* qb = &g_q[(bh * TT + qt0) * DD];
        const __half2 sc2 = __floats2half2_rn(0.18033688f, 0.18033688f);
        #pragma unroll
        for (int p = 0; p < 4; p++) {
            int idx = tid + p * 256;            // 0..1023 over 128x8 chunks
            int r = idx >> 3, c = idx & 7;
            uint4 v = *(const uint4*)&qb[r * DD + c * 8];
            __half2* hp = (__half2*)&v;
            #pragma unroll
            for (int i = 0; i < 4; i++) hp[i] = __hmul2(hp[i], sc2);
            *(uint4*)((char*)&Ks[0][0] + (r >> 6) * KBUF + swz(r & 63, c)) = v;
        }
    }
    __syncthreads();
    uint32_t qa[4][4];
    {
        int row = warp * 16 + lrowA;            // 0..127
        uint32_t qbase = ks_base + (row >> 6) * KBUF;
        int rl = row & 63;
        #pragma unroll
        for (int kc = 0; kc < 4; kc++) {
            int ch = 2 * kc + (lcol8A >> 3);
            ldm_x4(qa[kc], qbase + swz(rl, ch));
        }
    }
    __syncthreads();            // Q reads done before Ks reused for K

    load_kv(0, 0); cp_commit();
    load_kv(1, 1); cp_commit();

    float o[8][4] = {};
    float m0v = -1e30f, m1v = -1e30f, l0 = 0.f, l1 = 0.f;
    const int i0 = qt0 + warp * 16 + g;
    const int i1 = i0 + 8;

    for (int jt = 0; jt < njt; jt++) {
        cp_wait<1>();
        __syncthreads();

        if (jt + 2 < njt) load_kv(jt + 2, (jt + 2) % KVSTG);
        cp_commit();

        const int st = jt % KVSTG;
        const uint32_t kst = ks_base + st * KBUF;
        const uint32_t vst = vs_base + st * KBUF;

        // --- S = Q K^T (log2 domain) ---
        float s[8][4] = {};
        #pragma unroll
        for (int kc = 0; kc < 4; kc++) {
            uint32_t kf[4][4];
            #pragma unroll
            for (int np = 0; np < 4; np++) {
                int key = np * 16 + lrowK;
                int ch  = 2 * kc + (lcol8K >> 3);
                ldm_x4(kf[np], kst + swz(key, ch));
            }
            #pragma unroll
            for (int nt = 0; nt < 8; nt++)
                mma_f16(s[nt], qa[kc], &kf[nt >> 1][(nt & 1) * 2]);
        }

        // --- causal mask (tiles that can cross this warp's diagonal) ---
        if (jt * 64 + 63 > i0) {
            #pragma unroll
            for (int nt = 0; nt < 8; nt++) {
                int j = jt * 64 + nt * 8 + 2 * tg;
                if (j     > i0) s[nt][0] = -1e30f;
                if (j + 1 > i0) s[nt][1] = -1e30f;
                if (j     > i1) s[nt][2] = -1e30f;
                if (j + 1 > i1) s[nt][3] = -1e30f;
            }
        }

        // --- online softmax (exp2 domain) ---
        float rmax0 = -1e30f, rmax1 = -1e30f;
        #pragma unroll
        for (int nt = 0; nt < 8; nt++) {
            rmax0 = fmaxf(rmax0, fmaxf(s[nt][0], s[nt][1]));
            rmax1 = fmaxf(rmax1, fmaxf(s[nt][2], s[nt][3]));
        }
        rmax0 = fmaxf(rmax0, __shfl_xor_sync(0xffffffffu, rmax0, 1));
        rmax0 = fmaxf(rmax0, __shfl_xor_sync(0xffffffffu, rmax0, 2));
        rmax1 = fmaxf(rmax1, __shfl_xor_sync(0xffffffffu, rmax1, 1));
        rmax1 = fmaxf(rmax1, __shfl_xor_sync(0xffffffffu, rmax1, 2));

        float mn0 = fmaxf(m0v, rmax0);
        float mn1 = fmaxf(m1v, rmax1);
        float al0 = exp2f(m0v - mn0);
        float al1 = exp2f(m1v - mn1);

        float ls0 = 0.f, ls1 = 0.f;
        #pragma unroll
        for (int nt = 0; nt < 8; nt++) {
            s[nt][0] = exp2f(s[nt][0] - mn0);
            s[nt][1] = exp2f(s[nt][1] - mn0);
            s[nt][2] = exp2f(s[nt][2] - mn1);
            s[nt][3] = exp2f(s[nt][3] - mn1);
            ls0 += s[nt][0] + s[nt][1];
            ls1 += s[nt][2] + s[nt][3];
        }
        ls0 += __shfl_xor_sync(0xffffffffu, ls0, 1);
        ls0 += __shfl_xor_sync(0xffffffffu, ls0, 2);
        ls1 += __shfl_xor_sync(0xffffffffu, ls1, 1);
        ls1 += __shfl_xor_sync(0xffffffffu, ls1, 2);

        l0 = l0 * al0 + ls0;  m0v = mn0;
        l1 = l1 * al1 + ls1;  m1v = mn1;

        #pragma unroll
        for (int nt = 0; nt < 8; nt++) {
            o[nt][0] *= al0; o[nt][1] *= al0;
            o[nt][2] *= al1; o[nt][3] *= al1;
        }

        // --- O += P V (direct pack of S into A-frags) ---
        #pragma unroll
        for (int kc = 0; kc < 4; kc++) {
            uint32_t pa[4];
            pa[0] = pack_h2(s[2*kc  ][0], s[2*kc  ][1]);
            pa[1] = pack_h2(s[2*kc  ][2], s[2*kc  ][3]);
            pa[2] = pack_h2(s[2*kc+1][0], s[2*kc+1][1]);
            pa[3] = pack_h2(s[2*kc+1][2], s[2*kc+1][3]);
            uint32_t vf[4][4];
            #pragma unroll
            for (int np = 0; np < 4; np++) {
                int key = kc * 16 + lrowA;
                int ch  = 2 * np + (lcol8A >> 3);
                ldm_x4_t(vf[np], vst + swz(key, ch));
            }
            #pragma unroll
            for (int nt = 0; nt < 8; nt++)
                mma_f16(o[nt], pa, &vf[nt >> 1][(nt & 1) * 2]);
        }
    }

    // --- normalize + store to g_att ---
    const float inv0 = 1.f / l0;
    const float inv1 = 1.f / l1;
    const int b = bh >> 4;
    const int h = bh & 15;
    const int r0 = qt0 + warp * 16 + g;
    __half* ob0 = &g_att[(b * TT + r0) * CC + h * DD];
    __half* ob1 = &g_att[(b * TT + r0 + 8) * CC + h * DD];
    #pragma unroll
    for (int nt = 0; nt < 8; nt++) {
        int col = nt * 8 + 2 * tg;
        *(uint32_t*)&ob0[col] = pack_h2(o[nt][0] * inv0, o[nt][1] * inv0);
        *(uint32_t*)&ob1[col] = pack_h2(o[nt][2] * inv1, o[nt][3] * inv1);
    }
}

// ---------------------------------------------------------------------------
extern "C" void kernel_launch(void* const* d_in, const int* in_sizes, int n_in,
                              void* d_out, int out_size)
{
    const float* x  = (const float*)d_in[0];
    const float* Wq = (const float*)d_in[1];
    const float* Wk = (const float*)d_in[2];
    const float* Wv = (const float*)d_in[3];
    const float* Wp = (const float*)d_in[4];
    const float* bp = (const float*)d_in[5];
    float* out = (float*)d_out;

    (void)in_sizes; (void)n_in; (void)out_size;

    // 0) one fused fp32 -> fp16 conversion pass
    cvt_all<<<2048, 256>>>((const float4*)x,  (const float4*)Wq,
                           (const float4*)Wk, (const float4*)Wv,
                           (const float4*)Wp);

    // 1) fused QKV projections (fp16 MMA, 8 warps): N=3072, M=4096
    gemm_tc<1><<<dim3(24, 32), 256>>>(nullptr, nullptr);

    // 2) causal flash attention (fp16 MMA, 128q blocks): 16 x 32
    attn_tc<<<dim3(16, 32), 256>>>();

    // 3) output projection + bias (fp16 MMA, 8 warps): N=1024
    gemm_tc<0><<<dim3(8, 32), 256>>>(bp, out);
}

// round 12
// speedup vs baseline: 1.1170x; 1.1170x over previous
#include <cuda_runtime.h>
#include <cuda_fp16.h>
#include <cstdint>

// Problem constants
#define BB 2
#define TT 2048
#define CC 1024
#define HH 16
#define DD 64
#define MM (BB*TT)

// Scratch (static __device__ — no runtime allocation). fp16 everywhere.
__device__ __half g_xh[MM*CC];
__device__ __half g_wqh[HH*CC*DD];
__device__ __half g_wkh[HH*CC*DD];
__device__ __half g_wvh[HH*CC*DD];
__device__ __half g_wph[CC*CC];
__device__ __half g_q[BB*HH*TT*DD];     // [B,H,T,D]
__device__ __half g_k[BB*HH*TT*DD];
__device__ __half g_v[BB*HH*TT*DD];
__device__ __half g_att[BB*TT*CC];      // [B,T,C]

// ---------------------------------------------------------------------------
// helpers
// ---------------------------------------------------------------------------
__device__ __forceinline__ void mma_f16(float* d, const uint32_t* a, const uint32_t* b) {
    asm volatile(
        "mma.sync.aligned.m16n8k16.row.col.f32.f16.f16.f32 "
        "{%0,%1,%2,%3}, {%4,%5,%6,%7}, {%8,%9}, {%0,%1,%2,%3};"
        : "+f"(d[0]), "+f"(d[1]), "+f"(d[2]), "+f"(d[3])
        : "r"(a[0]), "r"(a[1]), "r"(a[2]), "r"(a[3]),
          "r"(b[0]), "r"(b[1]));
}
__device__ __forceinline__ void ldm_x4(uint32_t* r, uint32_t addr) {
    asm volatile(
        "ldmatrix.sync.aligned.m8n8.x4.shared.b16 {%0,%1,%2,%3}, [%4];"
        : "=r"(r[0]), "=r"(r[1]), "=r"(r[2]), "=r"(r[3]) : "r"(addr));
}
__device__ __forceinline__ void ldm_x4_t(uint32_t* r, uint32_t addr) {
    asm volatile(
        "ldmatrix.sync.aligned.m8n8.x4.trans.shared.b16 {%0,%1,%2,%3}, [%4];"
        : "=r"(r[0]), "=r"(r[1]), "=r"(r[2]), "=r"(r[3]) : "r"(addr));
}
__device__ __forceinline__ uint32_t pack_h2(float a, float b) {
    __half2 h = __floats2half2_rn(a, b);
    return *(uint32_t*)&h;
}
__device__ __forceinline__ void cp16(uint32_t dst, const void* src) {
    asm volatile("cp.async.cg.shared.global [%0], [%1], 16;" :: "r"(dst), "l"(src));
}
__device__ __forceinline__ void cp_commit() {
    asm volatile("cp.async.commit_group;");
}
template<int N> __device__ __forceinline__ void cp_wait() {
    asm volatile("cp.async.wait_group %0;" :: "n"(N));
}

// ---------------------------------------------------------------------------
// Fused fp32 -> fp16 conversion (one launch for all five tensors)
// ---------------------------------------------------------------------------
__global__ void cvt_all(const float4* __restrict__ x,  const float4* __restrict__ wq,
                        const float4* __restrict__ wk, const float4* __restrict__ wv,
                        const float4* __restrict__ wp)
{
    const int N_X = MM * CC / 4;
    const int N_W = HH * CC * DD / 4;
    const int N_P = CC * CC / 4;
    const int total = N_X + 3 * N_W + N_P;
    int i = blockIdx.x * blockDim.x + threadIdx.x;
    const int stride = gridDim.x * blockDim.x;
    for (; i < total; i += stride) {
        const float4* src; uint2* dst; int j = i;
        if (j < N_X)              { src = x;  dst = (uint2*)g_xh; }
        else if ((j -= N_X) < N_W){ src = wq; dst = (uint2*)g_wqh; }
        else if ((j -= N_W) < N_W){ src = wk; dst = (uint2*)g_wkh; }
        else if ((j -= N_W) < N_W){ src = wv; dst = (uint2*)g_wvh; }
        else                      { j -= N_W; src = wp; dst = (uint2*)g_wph; }
        float4 v = src[j];
        uint2 r;
        r.x = pack_h2(v.x, v.y);
        r.y = pack_h2(v.z, v.w);
        dst[j] = r;
    }
}

// ---------------------------------------------------------------------------
// GEMM (fp16 MMA, 3-stage cp.async, BK=32, ONE barrier per 64 warp-MMAs).
// BM=128, BN=128. 128 threads = 4 warps; warp tile 64(m) x 64(n).
// Dynamic SMEM: 3 x (10.0 + 8.5) KB = 55.5 KB; 2 CTAs/SM (8 warps).
// SA_H=40: 80B rows, ldmatrix row banks {0,20,8,28,16,4,24,12} conflict-free.
// ---------------------------------------------------------------------------
#define SA_H 40
#define SB_H 136
#define NSTG 3
#define ABUF_B (128 * SA_H * 2)
#define BBUF_B (32 * SB_H * 2)
#define GSMEM  (NSTG * (ABUF_B + BBUF_B))

template<int IS_QKV>
__global__ __launch_bounds__(128, 2) void gemm_tc(
    const float* __restrict__ bp,
    float* __restrict__ out)
{
    extern __shared__ __half smem[];
    __half* As = smem;                              // NSTG x 128 x SA_H
    __half* Bs = smem + NSTG * 128 * SA_H;          // NSTG x 32 x SB_H

    const int tid  = threadIdx.x;
    const int lane = tid & 31;
    const int warp = tid >> 5;          // 0..3
    const int wm = warp & 1;
    const int wn = warp >> 1;
    const int g  = lane >> 2;
    const int tg = lane & 3;

    const int m0 = blockIdx.y * 128;
    const int n0 = blockIdx.x * 128;

    const __half* A = IS_QKV ? g_xh : g_att;
    const __half* W;
    int h0 = 0, sel = 0;
    if (IS_QKV) {
        sel = n0 >> 10;
        h0  = (n0 & 1023) >> 6;
        W   = (sel == 0 ? g_wqh : (sel == 1 ? g_wkh : g_wvh));
    } else {
        W = g_wph;
    }

    // cp.async mapping: A 128x32 halves (512 chunks), B 32x128 (512 chunks)
    const int a_r  = tid >> 2;              // 0..31 (+32 per pass)
    const int a_c8 = (tid & 3) * 8;
    const int b_r  = tid >> 4;              // 0..7 (+8 per pass)
    const int b_c8 = (tid & 15) * 8;

    const int lrow  = (lane & 7) + ((lane >> 3) & 1) * 8;
    const int lcol8 = ((lane >> 4) & 1) * 8;
    const uint32_t a_base = (uint32_t)__cvta_generic_to_shared(As);
    const uint32_t b_base = (uint32_t)__cvta_generic_to_shared(Bs);

    auto load_stage = [&](int k0, int st) {
        #pragma unroll
        for (int p = 0; p < 4; p++) {
            int r = a_r + p * 32;
            cp16(a_base + st * ABUF_B + (r * SA_H + a_c8) * 2,
                 &A[(m0 + r) * CC + k0 + a_c8]);
        }
        #pragma unroll
        for (int p = 0; p < 4; p++) {
            int r = b_r + p * 8;
            const __half* src;
            if (IS_QKV) {
                int h = h0 + (b_c8 >> 6);
                int d = b_c8 & 63;
                src = &W[(h * CC + (k0 + r)) * DD + d];
            } else {
                src = &W[(k0 + r) * CC + n0 + b_c8];
            }
            cp16(b_base + st * BBUF_B + (r * SB_H + b_c8) * 2, src);
        }
    };

    float acc[4][8][4] = {};

    load_stage(0, 0);  cp_commit();
    load_stage(32, 1); cp_commit();

    const int NIT = CC / 32;   // 32
    for (int it = 0; it < NIT; it++) {
        cp_wait<1>();
        __syncthreads();

        if (it + 2 < NIT) load_stage((it + 2) * 32, (it + 2) % NSTG);
        cp_commit();

        const int st = it % NSTG;
        // two k8x2 chunks per stage; chunk1 ldm overlaps chunk0 MMAs
        #pragma unroll
        for (int kc = 0; kc < 2; kc++) {
            uint32_t af[4][4];
            #pragma unroll
            for (int mt = 0; mt < 4; mt++) {
                int row = wm * 64 + mt * 16 + lrow;
                ldm_x4(af[mt], a_base + st * ABUF_B + (row * SA_H + kc * 16 + lcol8) * 2);
            }
            uint32_t bf[4][4];
            #pragma unroll
            for (int np = 0; np < 4; np++) {
                int col = wn * 64 + np * 16 + lcol8;
                ldm_x4_t(bf[np], b_base + st * BBUF_B + ((kc * 16 + lrow) * SB_H + col) * 2);
            }
            #pragma unroll
            for (int nt = 0; nt < 8; nt++) {
                const uint32_t* bb = &bf[nt >> 1][(nt & 1) * 2];
                #pragma unroll
                for (int mt = 0; mt < 4; mt++)
                    mma_f16(acc[mt][nt], af[mt], bb);
            }
        }
    }

    // ---- epilogue ----
    #pragma unroll
    for (int mt = 0; mt < 4; mt++) {
        int mm = m0 + wm * 64 + mt * 16 + g;
        if (IS_QKV) {
            __half* outBuf = (sel == 0 ? g_q : (sel == 1 ? g_k : g_v));
            int b = mm >> 11;
            int t = mm & 2047;
            int h = h0 + wn;
            #pragma unroll
            for (int nt = 0; nt < 8; nt++) {
                int d = nt * 8 + 2 * tg;
                *(uint32_t*)&outBuf[((b * HH + h) * TT + t) * DD + d] =
                    pack_h2(acc[mt][nt][0], acc[mt][nt][1]);
                *(uint32_t*)&outBuf[((b * HH + h) * TT + t + 8) * DD + d] =
                    pack_h2(acc[mt][nt][2], acc[mt][nt][3]);
            }
        } else {
            #pragma unroll
            for (int nt = 0; nt < 8; nt++) {
                int col = n0 + wn * 64 + nt * 8 + 2 * tg;
                float b0 = bp[col], b1 = bp[col + 1];
                *(float2*)&out[mm * CC + col] =
                    make_float2(acc[mt][nt][0] + b0, acc[mt][nt][1] + b1);
                *(float2*)&out[(mm + 8) * CC + col] =
                    make_float2(acc[mt][nt][2] + b0, acc[mt][nt][3] + b1);
            }
        }
    }
}

// ---------------------------------------------------------------------------
// Flash attention (causal), fp16 MMA, 3-stage swizzled KV pipeline (R10 form).
// 128 threads = 4 warps; 64 queries per CTA; 64-key tiles; exp2 softmax.
// ---------------------------------------------------------------------------
#define KVSTG 3

__device__ __forceinline__ uint32_t swz(int row, int chunk) {
    return (uint32_t)(row * 128 + ((chunk ^ (row & 7)) << 4));
}

__global__ __launch_bounds__(128, 3) void attn_tc()
{
    __shared__ __half Ks[KVSTG][64 * 64];   // 3 x 8 KB
    __shared__ __half Vs[KVSTG][64 * 64];   // 3 x 8 KB  (48 KB total)

    const int tid  = threadIdx.x;
    const int lane = tid & 31;
    const int warp = tid >> 5;
    const int g  = lane >> 2;
    const int tg = lane & 3;

    const int qt  = blockIdx.x;
    const int bh  = blockIdx.y;
    const int qt0 = qt * 64;

    const uint32_t ks_base = (uint32_t)__cvta_generic_to_shared(&Ks[0][0]);
    const uint32_t vs_base = (uint32_t)__cvta_generic_to_shared(&Vs[0][0]);
    const uint32_t KBUF = 64 * 64 * 2;
    const int lrowA  = (lane & 7) + ((lane >> 3) & 1) * 8;
    const int lcol8A = ((lane >> 4) & 1) * 8;
    const int lrowK  = (lane & 7) + ((lane >> 4) & 1) * 8;
    const int lcol8K = ((lane >> 3) & 1) * 8;

    const int t_r = tid >> 3;
    const int t_c = tid & 7;

    auto load_kv = [&](int jt, int st) {
        const __half* kb = &g_k[(bh * TT + jt * 64) * DD];
        const __half* vb = &g_v[(bh * TT + jt * 64) * DD];
        #pragma unroll
        for (int p = 0; p < 4; p++) {
            int r = t_r + p * 16;
            cp16(ks_base + st * KBUF + swz(r, t_c), &kb[r * DD + t_c * 8]);
            cp16(vs_base + st * KBUF + swz(r, t_c), &vb[r * DD + t_c * 8]);
        }
    };

    // --- stage Q (scale = log2(e)/8) into Ks[0], extract A-frags ---
    {
        const __half* qb = &g_q[(bh * TT + qt0) * DD];
        const __half2 sc2 = __floats2half2_rn(0.18033688f, 0.18033688f);
        #pragma unroll
        for (int p = 0; p < 4; p++) {
            int idx = tid + p * 128;
            int r = idx >> 3, c = idx & 7;
            uint4 v = *(const uint4*)&qb[r * DD + c * 8];
            __half2* hp = (__half2*)&v;
            #pragma unroll
            for (int i = 0; i < 4; i++) hp[i] = __hmul2(hp[i], sc2);
            *(uint4*)((char*)&Ks[0][0] + swz(r, c)) = v;
        }
    }
    __syncthreads();
    uint32_t qa[4][4];
    #pragma unroll
    for (int kc = 0; kc < 4; kc++) {
        int row = warp * 16 + lrowA;
        int ch  = 2 * kc + (lcol8A >> 3);
        ldm_x4(qa[kc], ks_base + swz(row, ch));
    }
    __syncthreads();

    load_kv(0, 0); cp_commit();
    if (qt >= 1) load_kv(1, 1);
    cp_commit();

    float o[8][4] = {};
    float m0v = -1e30f, m1v = -1e30f, l0 = 0.f, l1 = 0.f;
    const int i0 = qt0 + warp * 16 + g;
    const int i1 = i0 + 8;

    for (int jt = 0; jt <= qt; jt++) {
        cp_wait<1>();
        __syncthreads();

        if (jt + 2 <= qt) load_kv(jt + 2, (jt + 2) % KVSTG);
        cp_commit();

        const int st = jt % KVSTG;
        const uint32_t kst = ks_base + st * KBUF;
        const uint32_t vst = vs_base + st * KBUF;

        float s[8][4] = {};
        #pragma unroll
        for (int kc = 0; kc < 4; kc++) {
            uint32_t kf[4][4];
            #pragma unroll
            for (int np = 0; np < 4; np++) {
                int key = np * 16 + lrowK;
                int ch  = 2 * kc + (lcol8K >> 3);
                ldm_x4(kf[np], kst + swz(key, ch));
            }
            #pragma unroll
            for (int nt = 0; nt < 8; nt++)
                mma_f16(s[nt], qa[kc], &kf[nt >> 1][(nt & 1) * 2]);
        }

        if (jt == qt) {
            #pragma unroll
            for (int nt = 0; nt < 8; nt++) {
                int j = qt0 + nt * 8 + 2 * tg;
                if (j     > i0) s[nt][0] = -1e30f;
                if (j + 1 > i0) s[nt][1] = -1e30f;
                if (j     > i1) s[nt][2] = -1e30f;
                if (j + 1 > i1) s[nt][3] = -1e30f;
            }
        }

        float rmax0 = -1e30f, rmax1 = -1e30f;
        #pragma unroll
        for (int nt = 0; nt < 8; nt++) {
            rmax0 = fmaxf(rmax0, fmaxf(s[nt][0], s[nt][1]));
            rmax1 = fmaxf(rmax1, fmaxf(s[nt][2], s[nt][3]));
        }
        rmax0 = fmaxf(rmax0, __shfl_xor_sync(0xffffffffu, rmax0, 1));
        rmax0 = fmaxf(rmax0, __shfl_xor_sync(0xffffffffu, rmax0, 2));
        rmax1 = fmaxf(rmax1, __shfl_xor_sync(0xffffffffu, rmax1, 1));
        rmax1 = fmaxf(rmax1, __shfl_xor_sync(0xffffffffu, rmax1, 2));

        float mn0 = fmaxf(m0v, rmax0);
        float mn1 = fmaxf(m1v, rmax1);
        float al0 = exp2f(m0v - mn0);
        float al1 = exp2f(m1v - mn1);

        float ls0 = 0.f, ls1 = 0.f;
        #pragma unroll
        for (int nt = 0; nt < 8; nt++) {
            s[nt][0] = exp2f(s[nt][0] - mn0);
            s[nt][1] = exp2f(s[nt][1] - mn0);
            s[nt][2] = exp2f(s[nt][2] - mn1);
            s[nt][3] = exp2f(s[nt][3] - mn1);
            ls0 += s[nt][0] + s[nt][1];
            ls1 += s[nt][2] + s[nt][3];
        }
        ls0 += __shfl_xor_sync(0xffffffffu, ls0, 1);
        ls0 += __shfl_xor_sync(0xffffffffu, ls0, 2);
        ls1 += __shfl_xor_sync(0xffffffffu, ls1, 1);
        ls1 += __shfl_xor_sync(0xffffffffu, ls1, 2);

        l0 = l0 * al0 + ls0;  m0v = mn0;
        l1 = l1 * al1 + ls1;  m1v = mn1;

        #pragma unroll
        for (int nt = 0; nt < 8; nt++) {
            o[nt][0] *= al0; o[nt][1] *= al0;
            o[nt][2] *= al1; o[nt][3] *= al1;
        }

        #pragma unroll
        for (int kc = 0; kc < 4; kc++) {
            uint32_t pa[4];
            pa[0] = pack_h2(s[2*kc  ][0], s[2*kc  ][1]);
            pa[1] = pack_h2(s[2*kc  ][2], s[2*kc  ][3]);
            pa[2] = pack_h2(s[2*kc+1][0], s[2*kc+1][1]);
            pa[3] = pack_h2(s[2*kc+1][2], s[2*kc+1][3]);
            uint32_t vf[4][4];
            #pragma unroll
            for (int np = 0; np < 4; np++) {
                int key = kc * 16 + lrowA;
                int ch  = 2 * np + (lcol8A >> 3);
                ldm_x4_t(vf[np], vst + swz(key, ch));
            }
            #pragma unroll
            for (int nt = 0; nt < 8; nt++)
                mma_f16(o[nt], pa, &vf[nt >> 1][(nt & 1) * 2]);
        }
    }

    // --- normalize + store to g_att ---
    const float inv0 = 1.f / l0;
    const float inv1 = 1.f / l1;
    const int b = bh >> 4;
    const int h = bh & 15;
    const int r0 = qt0 + warp * 16 + g;
    __half* ob0 = &g_att[(b * TT + r0) * CC + h * DD];
    __half* ob1 = &g_att[(b * TT + r0 + 8) * CC + h * DD];
    #pragma unroll
    for (int nt = 0; nt < 8; nt++) {
        int col = nt * 8 + 2 * tg;
        *(uint32_t*)&ob0[col] = pack_h2(o[nt][0] * inv0, o[nt][1] * inv0);
        *(uint32_t*)&ob1[col] = pack_h2(o[nt][2] * inv1, o[nt][3] * inv1);
    }
}

// ---------------------------------------------------------------------------
extern "C" void kernel_launch(void* const* d_in, const int* in_sizes, int n_in,
                              void* d_out, int out_size)
{
    const float* x  = (const float*)d_in[0];
    const float* Wq = (const float*)d_in[1];
    const float* Wk = (const float*)d_in[2];
    const float* Wv = (const float*)d_in[3];
    const float* Wp = (const float*)d_in[4];
    const float* bp = (const float*)d_in[5];
    float* out = (float*)d_out;

    (void)in_sizes; (void)n_in; (void)out_size;

    cudaFuncSetAttribute(gemm_tc<1>, cudaFuncAttributeMaxDynamicSharedMemorySize, GSMEM);
    cudaFuncSetAttribute(gemm_tc<0>, cudaFuncAttributeMaxDynamicSharedMemorySize, GSMEM);

    // 0) one fused fp32 -> fp16 conversion pass
    cvt_all<<<2048, 256>>>((const float4*)x,  (const float4*)Wq,
                           (const float4*)Wk, (const float4*)Wv,
                           (const float4*)Wp);

    // 1) fused QKV projections (fp16 MMA, BK=32, 3-stage): N=3072, M=4096
    gemm_tc<1><<<dim3(24, 32), 128, GSMEM>>>(nullptr, nullptr);

    // 2) causal flash attention (fp16 MMA, 3-stage swizzled KV)
    attn_tc<<<dim3(32, 32), 128>>>();

    // 3) output projection + bias (fp16 MMA, BK=32, 3-stage): N=1024
    gemm_tc<0><<<dim3(8, 32), 128, GSMEM>>>(bp, out);
}

// round 15
// speedup vs baseline: 1.1400x; 1.0206x over previous
#include <cuda_runtime.h>
#include <cuda_fp16.h>
#include <cstdint>

// Problem constants
#define BB 2
#define TT 2048
#define CC 1024
#define HH 16
#define DD 64
#define MM (BB*TT)

// Scratch (static __device__ — no runtime allocation). fp16 everywhere.
__device__ __half g_xh[MM*CC];
__device__ __half g_wqh[HH*CC*DD];
__device__ __half g_wkh[HH*CC*DD];
__device__ __half g_wvh[HH*CC*DD];
__device__ __half g_wph[CC*CC];
__device__ __half g_q[BB*HH*TT*DD];     // [B,H,T,D]
__device__ __half g_k[BB*HH*TT*DD];
__device__ __half g_v[BB*HH*TT*DD];
__device__ __half g_att[BB*TT*CC];      // [B,T,C]

// ---------------------------------------------------------------------------
// helpers
// ---------------------------------------------------------------------------
__device__ __forceinline__ void mma_f16(float* d, const uint32_t* a, const uint32_t* b) {
    asm volatile(
        "mma.sync.aligned.m16n8k16.row.col.f32.f16.f16.f32 "
        "{%0,%1,%2,%3}, {%4,%5,%6,%7}, {%8,%9}, {%0,%1,%2,%3};"
        : "+f"(d[0]), "+f"(d[1]), "+f"(d[2]), "+f"(d[3])
        : "r"(a[0]), "r"(a[1]), "r"(a[2]), "r"(a[3]),
          "r"(b[0]), "r"(b[1]));
}
__device__ __forceinline__ void ldm_x4(uint32_t* r, uint32_t addr) {
    asm volatile(
        "ldmatrix.sync.aligned.m8n8.x4.shared.b16 {%0,%1,%2,%3}, [%4];"
        : "=r"(r[0]), "=r"(r[1]), "=r"(r[2]), "=r"(r[3]) : "r"(addr));
}
__device__ __forceinline__ void ldm_x4_t(uint32_t* r, uint32_t addr) {
    asm volatile(
        "ldmatrix.sync.aligned.m8n8.x4.trans.shared.b16 {%0,%1,%2,%3}, [%4];"
        : "=r"(r[0]), "=r"(r[1]), "=r"(r[2]), "=r"(r[3]) : "r"(addr));
}
__device__ __forceinline__ uint32_t pack_h2(float a, float b) {
    __half2 h = __floats2half2_rn(a, b);
    return *(uint32_t*)&h;
}
__device__ __forceinline__ void cp16(uint32_t dst, const void* src) {
    asm volatile("cp.async.cg.shared.global [%0], [%1], 16;" :: "r"(dst), "l"(src));
}
__device__ __forceinline__ void cp_commit() {
    asm volatile("cp.async.commit_group;");
}
template<int N> __device__ __forceinline__ void cp_wait() {
    asm volatile("cp.async.wait_group %0;" :: "n"(N));
}

// ---------------------------------------------------------------------------
// Fused fp32 -> fp16 conversion (one launch for all five tensors)
// ---------------------------------------------------------------------------
__global__ void cvt_all(const float4* __restrict__ x,  const float4* __restrict__ wq,
                        const float4* __restrict__ wk, const float4* __restrict__ wv,
                        const float4* __restrict__ wp)
{
    const int N_X = MM * CC / 4;
    const int N_W = HH * CC * DD / 4;
    const int N_P = CC * CC / 4;
    const int total = N_X + 3 * N_W + N_P;
    int i = blockIdx.x * blockDim.x + threadIdx.x;
    const int stride = gridDim.x * blockDim.x;
    for (; i < total; i += stride) {
        const float4* src; uint2* dst; int j = i;
        if (j < N_X)              { src = x;  dst = (uint2*)g_xh; }
        else if ((j -= N_X) < N_W){ src = wq; dst = (uint2*)g_wqh; }
        else if ((j -= N_W) < N_W){ src = wk; dst = (uint2*)g_wkh; }
        else if ((j -= N_W) < N_W){ src = wv; dst = (uint2*)g_wvh; }
        else                      { j -= N_W; src = wp; dst = (uint2*)g_wph; }
        float4 v = src[j];
        uint2 r;
        r.x = pack_h2(v.x, v.y);
        r.y = pack_h2(v.z, v.w);
        dst[j] = r;
    }
}

// ---------------------------------------------------------------------------
// GEMM (fp16 MMA, 3-stage cp.async, BK=16, ONE barrier per iteration).
// BM=128, BN=128. 128 threads = 4 warps; warp tile 64(m) x 64(n).
// SA_H=24: 48B rows, 16B-aligned, ldmatrix row banks 12r mod 32 distinct.
// ---------------------------------------------------------------------------
#define SA_H 24
#define SB_H 136
#define NSTG 3

template<int IS_QKV>
__global__ __launch_bounds__(128, 2) void gemm_tc(
    const float* __restrict__ bp,
    float* __restrict__ out)
{
    __shared__ __half As[NSTG][128 * SA_H];   // 3 x 6.0 KB
    __shared__ __half Bs[NSTG][16 * SB_H];    // 3 x 4.25 KB  (31.5 KB total)

    const int tid  = threadIdx.x;
    const int lane = tid & 31;
    const int warp = tid >> 5;
    const int wm = warp & 1;
    const int wn = warp >> 1;
    const int g  = lane >> 2;
    const int tg = lane & 3;

    const int m0 = blockIdx.y * 128;
    const int n0 = blockIdx.x * 128;

    const __half* A = IS_QKV ? g_xh : g_att;
    const __half* W;
    int h0 = 0, sel = 0;
    if (IS_QKV) {
        sel = n0 >> 10;
        h0  = (n0 & 1023) >> 6;
        W   = (sel == 0 ? g_wqh : (sel == 1 ? g_wkh : g_wvh));
    } else {
        W = g_wph;
    }

    // cp.async mapping: A 128x16 halves (256 chunks), B 16x128 (256 chunks)
    const int a_r  = tid >> 1;              // 0..63 (+64)
    const int a_c8 = (tid & 1) * 8;
    const int b_r  = tid >> 4;              // 0..7 (+8)
    const int b_c8 = (tid & 15) * 8;

    const int lrow  = (lane & 7) + ((lane >> 3) & 1) * 8;
    const int lcol8 = ((lane >> 4) & 1) * 8;
    const uint32_t a_base = (uint32_t)__cvta_generic_to_shared(&As[0][0]);
    const uint32_t b_base = (uint32_t)__cvta_generic_to_shared(&Bs[0][0]);
    const uint32_t ABUF = 128 * SA_H * 2;
    const uint32_t BBUF = 16 * SB_H * 2;

    auto load_stage = [&](int k0, int st) {
        #pragma unroll
        for (int p = 0; p < 2; p++) {
            int r = a_r + p * 64;
            cp16(a_base + st * ABUF + (r * SA_H + a_c8) * 2,
                 &A[(m0 + r) * CC + k0 + a_c8]);
        }
        #pragma unroll
        for (int p = 0; p < 2; p++) {
            int r = b_r + p * 8;
            const __half* src;
            if (IS_QKV) {
                int h = h0 + (b_c8 >> 6);
                int d = b_c8 & 63;
                src = &W[(h * CC + (k0 + r)) * DD + d];
            } else {
                src = &W[(k0 + r) * CC + n0 + b_c8];
            }
            cp16(b_base + st * BBUF + (r * SB_H + b_c8) * 2, src);
        }
    };

    float acc[4][8][4] = {};

    // prologue: 2 real groups
    load_stage(0, 0);  cp_commit();
    load_stage(16, 1); cp_commit();

    const int NIT = CC / 16;   // 64
    for (int it = 0; it < NIT; it++) {
        cp_wait<1>();          // stage it's group retired
        __syncthreads();       // all warps done with stage (it-1)'s reads

        if (it + 2 < NIT) load_stage((it + 2) * 16, (it + 2) % NSTG);
        cp_commit();           // empty group on tail keeps wait invariant

        const int st = it % NSTG;
        uint32_t af[4][4];
        #pragma unroll
        for (int mt = 0; mt < 4; mt++) {
            int row = wm * 64 + mt * 16 + lrow;
            ldm_x4(af[mt], a_base + st * ABUF + (row * SA_H + lcol8) * 2);
        }
        uint32_t bf[4][4];
        #pragma unroll
        for (int np = 0; np < 4; np++) {
            int col = wn * 64 + np * 16 + lcol8;
            ldm_x4_t(bf[np], b_base + st * BBUF + (lrow * SB_H + col) * 2);
        }
        #pragma unroll
        for (int nt = 0; nt < 8; nt++) {
            const uint32_t* bb = &bf[nt >> 1][(nt & 1) * 2];
            #pragma unroll
            for (int mt = 0; mt < 4; mt++)
                mma_f16(acc[mt][nt], af[mt], bb);
        }
    }

    // ---- epilogue ----
    #pragma unroll
    for (int mt = 0; mt < 4; mt++) {
        int mm = m0 + wm * 64 + mt * 16 + g;
        if (IS_QKV) {
            __half* outBuf = (sel == 0 ? g_q : (sel == 1 ? g_k : g_v));
            int b = mm >> 11;
            int t = mm & 2047;
            int h = h0 + wn;
            #pragma unroll
            for (int nt = 0; nt < 8; nt++) {
                int d = nt * 8 + 2 * tg;
                *(uint32_t*)&outBuf[((b * HH + h) * TT + t) * DD + d] =
                    pack_h2(acc[mt][nt][0], acc[mt][nt][1]);
                *(uint32_t*)&outBuf[((b * HH + h) * TT + t + 8) * DD + d] =
                    pack_h2(acc[mt][nt][2], acc[mt][nt][3]);
            }
        } else {
            #pragma unroll
            for (int nt = 0; nt < 8; nt++) {
                int col = n0 + wn * 64 + nt * 8 + 2 * tg;
                float b0 = bp[col], b1 = bp[col + 1];
                *(float2*)&out[mm * CC + col] =
                    make_float2(acc[mt][nt][0] + b0, acc[mt][nt][1] + b1);
                *(float2*)&out[(mm + 8) * CC + col] =
                    make_float2(acc[mt][nt][2] + b0, acc[mt][nt][3] + b1);
            }
        }
    }
}

// ---------------------------------------------------------------------------
// Flash attention (causal), fp16 MMA, 3-stage swizzled KV pipeline,
// ONE barrier per key tile. 64x64-half tiles, 128B rows, SW128 XOR swizzle.
// Softmax in exp2 domain (log2(e)/8 folded into Q scale).
// Heavy-first scheduling: qt = gridDim.x-1-blockIdx.x so the 32-iteration
// CTAs enter the machine first (tighter makespan on the last wave).
// ---------------------------------------------------------------------------
#define KVSTG 3

__device__ __forceinline__ uint32_t swz(int row, int chunk) {
    return (uint32_t)(row * 128 + ((chunk ^ (row & 7)) << 4));
}

__global__ __launch_bounds__(128, 3) void attn_tc()
{
    __shared__ __half Ks[KVSTG][64 * 64];   // 3 x 8 KB
    __shared__ __half Vs[KVSTG][64 * 64];   // 3 x 8 KB  (48 KB total)

    const int tid  = threadIdx.x;
    const int lane = tid & 31;
    const int warp = tid >> 5;
    const int g  = lane >> 2;
    const int tg = lane & 3;

    const int qt  = (int)gridDim.x - 1 - (int)blockIdx.x;   // heavy-first
    const int bh  = blockIdx.y;
    const int qt0 = qt * 64;

    const uint32_t ks_base = (uint32_t)__cvta_generic_to_shared(&Ks[0][0]);
    const uint32_t vs_base = (uint32_t)__cvta_generic_to_shared(&Vs[0][0]);
    const uint32_t KBUF = 64 * 64 * 2;
    const int lrowA  = (lane & 7) + ((lane >> 3) & 1) * 8;
    const int lcol8A = ((lane >> 4) & 1) * 8;
    const int lrowK  = (lane & 7) + ((lane >> 4) & 1) * 8;
    const int lcol8K = ((lane >> 3) & 1) * 8;

    const int t_r = tid >> 3;
    const int t_c = tid & 7;

    auto load_kv = [&](int jt, int st) {
        const __half* kb = &g_k[(bh * TT + jt * 64) * DD];
        const __half* vb = &g_v[(bh * TT + jt * 64) * DD];
        #pragma unroll
        for (int p = 0; p < 4; p++) {
            int r = t_r + p * 16;
            cp16(ks_base + st * KBUF + swz(r, t_c), &kb[r * DD + t_c * 8]);
            cp16(vs_base + st * KBUF + swz(r, t_c), &vb[r * DD + t_c * 8]);
        }
    };

    // --- stage Q (scale = log2(e)/8 folded) into Ks[0], extract A-frags ---
    {
        const __half* qb = &g_q[(bh * TT + qt0) * DD];
        const __half2 sc2 = __floats2half2_rn(0.18033688f, 0.18033688f);
        #pragma unroll
        for (int p = 0; p < 4; p++) {
            int idx = tid + p * 128;
            int r = idx >> 3, c = idx & 7;
            uint4 v = *(const uint4*)&qb[r * DD + c * 8];
            __half2* hp = (__half2*)&v;
            #pragma unroll
            for (int i = 0; i < 4; i++) hp[i] = __hmul2(hp[i], sc2);
            *(uint4*)((char*)&Ks[0][0] + swz(r, c)) = v;
        }
    }
    __syncthreads();
    uint32_t qa[4][4];
    #pragma unroll
    for (int kc = 0; kc < 4; kc++) {
        int row = warp * 16 + lrowA;
        int ch  = 2 * kc + (lcol8A >> 3);
        ldm_x4(qa[kc], ks_base + swz(row, ch));
    }
    __syncthreads();            // Q reads done before Ks[0] reused for K

    // prologue: 2 real groups (guard jt=1 for qt=0)
    load_kv(0, 0); cp_commit();
    if (qt >= 1) load_kv(1, 1);
    cp_commit();

    float o[8][4] = {};
    float m0v = -1e30f, m1v = -1e30f, l0 = 0.f, l1 = 0.f;
    const int i0 = qt0 + warp * 16 + g;
    const int i1 = i0 + 8;

    for (int jt = 0; jt <= qt; jt++) {
        cp_wait<1>();
        __syncthreads();

        if (jt + 2 <= qt) load_kv(jt + 2, (jt + 2) % KVSTG);
        cp_commit();

        const int st = jt % KVSTG;
        const uint32_t kst = ks_base + st * KBUF;
        const uint32_t vst = vs_base + st * KBUF;

        // --- S = Q K^T (log2 domain) ---
        float s[8][4] = {};
        #pragma unroll
        for (int kc = 0; kc < 4; kc++) {
            uint32_t kf[4][4];
            #pragma unroll
            for (int np = 0; np < 4; np++) {
                int key = np * 16 + lrowK;
                int ch  = 2 * kc + (lcol8K >> 3);
                ldm_x4(kf[np], kst + swz(key, ch));
            }
            #pragma unroll
            for (int nt = 0; nt < 8; nt++)
                mma_f16(s[nt], qa[kc], &kf[nt >> 1][(nt & 1) * 2]);
        }

        if (jt == qt) {
            #pragma unroll
            for (int nt = 0; nt < 8; nt++) {
                int j = qt0 + nt * 8 + 2 * tg;
                if (j     > i0) s[nt][0] = -1e30f;
                if (j + 1 > i0) s[nt][1] = -1e30f;
                if (j     > i1) s[nt][2] = -1e30f;
                if (j + 1 > i1) s[nt][3] = -1e30f;
            }
        }

        // --- online softmax (exp2 domain) ---
        float rmax0 = -1e30f, rmax1 = -1e30f;
        #pragma unroll
        for (int nt = 0; nt < 8; nt++) {
            rmax0 = fmaxf(rmax0, fmaxf(s[nt][0], s[nt][1]));
            rmax1 = fmaxf(rmax1, fmaxf(s[nt][2], s[nt][3]));
        }
        rmax0 = fmaxf(rmax0, __shfl_xor_sync(0xffffffffu, rmax0, 1));
        rmax0 = fmaxf(rmax0, __shfl_xor_sync(0xffffffffu, rmax0, 2));
        rmax1 = fmaxf(rmax1, __shfl_xor_sync(0xffffffffu, rmax1, 1));
        rmax1 = fmaxf(rmax1, __shfl_xor_sync(0xffffffffu, rmax1, 2));

        float mn0 = fmaxf(m0v, rmax0);
        float mn1 = fmaxf(m1v, rmax1);
        float al0 = exp2f(m0v - mn0);
        float al1 = exp2f(m1v - mn1);

        float ls0 = 0.f, ls1 = 0.f;
        #pragma unroll
        for (int nt = 0; nt < 8; nt++) {
            s[nt][0] = exp2f(s[nt][0] - mn0);
            s[nt][1] = exp2f(s[nt][1] - mn0);
            s[nt][2] = exp2f(s[nt][2] - mn1);
            s[nt][3] = exp2f(s[nt][3] - mn1);
            ls0 += s[nt][0] + s[nt][1];
            ls1 += s[nt][2] + s[nt][3];
        }
        ls0 += __shfl_xor_sync(0xffffffffu, ls0, 1);
        ls0 += __shfl_xor_sync(0xffffffffu, ls0, 2);
        ls1 += __shfl_xor_sync(0xffffffffu, ls1, 1);
        ls1 += __shfl_xor_sync(0xffffffffu, ls1, 2);

        l0 = l0 * al0 + ls0;  m0v = mn0;
        l1 = l1 * al1 + ls1;  m1v = mn1;

        #pragma unroll
        for (int nt = 0; nt < 8; nt++) {
            o[nt][0] *= al0; o[nt][1] *= al0;
            o[nt][2] *= al1; o[nt][3] *= al1;
        }

        // --- O += P V (direct pack of S into A-frags) ---
        #pragma unroll
        for (int kc = 0; kc < 4; kc++) {
            uint32_t pa[4];
            pa[0] = pack_h2(s[2*kc  ][0], s[2*kc  ][1]);
            pa[1] = pack_h2(s[2*kc  ][2], s[2*kc  ][3]);
            pa[2] = pack_h2(s[2*kc+1][0], s[2*kc+1][1]);
            pa[3] = pack_h2(s[2*kc+1][2], s[2*kc+1][3]);
            uint32_t vf[4][4];
            #pragma unroll
            for (int np = 0; np < 4; np++) {
                int key = kc * 16 + lrowA;
                int ch  = 2 * np + (lcol8A >> 3);
                ldm_x4_t(vf[np], vst + swz(key, ch));
            }
            #pragma unroll
            for (int nt = 0; nt < 8; nt++)
                mma_f16(o[nt], pa, &vf[nt >> 1][(nt & 1) * 2]);
        }
    }

    // --- normalize + store to g_att ---
    const float inv0 = 1.f / l0;
    const float inv1 = 1.f / l1;
    const int b = bh >> 4;
    const int h = bh & 15;
    const int r0 = qt0 + warp * 16 + g;
    __half* ob0 = &g_att[(b * TT + r0) * CC + h * DD];
    __half* ob1 = &g_att[(b * TT + r0 + 8) * CC + h * DD];
    #pragma unroll
    for (int nt = 0; nt < 8; nt++) {
        int col = nt * 8 + 2 * tg;
        *(uint32_t*)&ob0[col] = pack_h2(o[nt][0] * inv0, o[nt][1] * inv0);
        *(uint32_t*)&ob1[col] = pack_h2(o[nt][2] * inv1, o[nt][3] * inv1);
    }
}

// ---------------------------------------------------------------------------
extern "C" void kernel_launch(void* const* d_in, const int* in_sizes, int n_in,
                              void* d_out, int out_size)
{
    const float* x  = (const float*)d_in[0];
    const float* Wq = (const float*)d_in[1];
    const float* Wk = (const float*)d_in[2];
    const float* Wv = (const float*)d_in[3];
    const float* Wp = (const float*)d_in[4];
    const float* bp = (const float*)d_in[5];
    float* out = (float*)d_out;

    (void)in_sizes; (void)n_in; (void)out_size;

    // 0) one fused fp32 -> fp16 conversion pass
    cvt_all<<<4096, 256>>>((const float4*)x,  (const float4*)Wq,
                           (const float4*)Wk, (const float4*)Wv,
                           (const float4*)Wp);

    // 1) fused QKV projections (fp16 MMA, 3-stage): N=3072, M=4096
    gemm_tc<1><<<dim3(24, 32), 128>>>(nullptr, nullptr);

    // 2) causal flash attention (fp16 MMA, 3-stage swizzled KV, heavy-first)
    attn_tc<<<dim3(32, 32), 128>>>();

    // 3) output projection + bias (fp16 MMA, 3-stage): N=1024
    gemm_tc<0><<<dim3(8, 32), 128>>>(bp, out);
}